// round 1
// baseline (speedup 1.0000x reference)
#include <cuda_runtime.h>
#include <cuda_bf16.h>
#include <math_constants.h>

// Problem constants
#define BATCH   8
#define SEQ     1024
#define DIM     512
#define HEADS   8
#define DHEAD   64
#define MROWS   (BATCH * SEQ)        // 8192
#define LOCALB  16

// Scratch (device globals; allocation is forbidden)
__device__ float g_q[MROWS * DIM];    // head-split [b][h][s][d]
__device__ float g_k[MROWS * DIM];
__device__ float g_v[MROWS * DIM];
__device__ float g_att[MROWS * DIM];  // merged-head [b][s][h*64+d]

// ---------------------------------------------------------------------------
// SGEMM: C[M,512] = A[M,512] @ W[512,512] + bias   (BM=128,BN=128,BK=8, 8x8 micro)
// headsplit=1: write C[((b*H+h)*S+s)*64 + d]; headsplit=0: C[row*512+col]
// ---------------------------------------------------------------------------
__device__ __forceinline__ void sgemm_body(
    const float* __restrict__ A, const float* __restrict__ W,
    const float* __restrict__ bias, float* __restrict__ C,
    int headsplit, int bx, int by)
{
    __shared__ float As[8][128];
    __shared__ float Bs[8][128];

    const int tid   = threadIdx.x;
    const int aRow  = tid >> 1;          // 0..127
    const int aCol4 = (tid & 1) * 4;     // 0 or 4
    const int bRow  = tid >> 5;          // 0..7
    const int bCol4 = (tid & 31) * 4;    // 0..124
    const int ty    = tid >> 4;          // 0..15
    const int tx    = tid & 15;          // 0..15

    const float* Aptr = A + (size_t)(by * 128) * DIM;
    const float* Wptr = W + bx * 128;

    float acc[8][8];
#pragma unroll
    for (int i = 0; i < 8; i++)
#pragma unroll
        for (int j = 0; j < 8; j++) acc[i][j] = 0.f;

    for (int k0 = 0; k0 < DIM; k0 += 8) {
        float4 a4 = *(const float4*)(Aptr + (size_t)aRow * DIM + k0 + aCol4);
        As[aCol4 + 0][aRow] = a4.x;
        As[aCol4 + 1][aRow] = a4.y;
        As[aCol4 + 2][aRow] = a4.z;
        As[aCol4 + 3][aRow] = a4.w;
        float4 b4 = *(const float4*)(Wptr + (size_t)(k0 + bRow) * DIM + bCol4);
        *(float4*)&Bs[bRow][bCol4] = b4;
        __syncthreads();
#pragma unroll
        for (int k = 0; k < 8; k++) {
            float ar[8], br[8];
#pragma unroll
            for (int i = 0; i < 8; i++) ar[i] = As[k][ty * 8 + i];
#pragma unroll
            for (int j = 0; j < 8; j++) br[j] = Bs[k][tx * 8 + j];
#pragma unroll
            for (int i = 0; i < 8; i++)
#pragma unroll
                for (int j = 0; j < 8; j++) acc[i][j] = fmaf(ar[i], br[j], acc[i][j]);
        }
        __syncthreads();
    }

#pragma unroll
    for (int i = 0; i < 8; i++) {
        int row = by * 128 + ty * 8 + i;
#pragma unroll
        for (int j = 0; j < 8; j++) {
            int col = bx * 128 + tx * 8 + j;
            float v = acc[i][j] + bias[col];
            if (headsplit) {
                int b = row >> 10, s = row & 1023;
                int h = col >> 6,  d = col & 63;
                C[((size_t)((b * HEADS + h) * SEQ + s) << 6) + d] = v;
            } else {
                C[(size_t)row * DIM + col] = v;
            }
        }
    }
}

__global__ __launch_bounds__(256) void proj_qkv_kernel(
    const float* __restrict__ q,  const float* __restrict__ k,  const float* __restrict__ v,
    const float* __restrict__ Wq, const float* __restrict__ Wk, const float* __restrict__ Wv,
    const float* __restrict__ bq, const float* __restrict__ bk, const float* __restrict__ bv)
{
    const float* A; const float* W; const float* bias; float* C;
    if (blockIdx.z == 0)      { A = q; W = Wq; bias = bq; C = g_q; }
    else if (blockIdx.z == 1) { A = k; W = Wk; bias = bk; C = g_k; }
    else                      { A = v; W = Wv; bias = bv; C = g_v; }
    sgemm_body(A, W, bias, C, 1, blockIdx.x, blockIdx.y);
}

__global__ __launch_bounds__(256) void out_proj_kernel(
    const float* __restrict__ Wo, const float* __restrict__ bo, float* __restrict__ out)
{
    sgemm_body(g_att, Wo, bo, out, 0, blockIdx.x, blockIdx.y);
}

// ---------------------------------------------------------------------------
// Sparse attention: one warp per (b, h, s) query.
// Neighbor set for query s (origin shape 4x16x16, idx = t*256 + r*16 + c):
//   band:   j = s - d,    d in [0, min(16, s)]
//   rows:   j = s - 16*m, m in [2, r]           (m=1 covered by band)
//   frames: j = s - 256*m, m in [1, t]
// <= 34 neighbors, duplicate-free.
// ---------------------------------------------------------------------------
#define FULLMASK 0xffffffffu

__global__ __launch_bounds__(256) void sparse_attn_kernel()
{
    const int warp = threadIdx.x >> 5;
    const int lane = threadIdx.x & 31;
    const int gw   = blockIdx.x * 8 + warp;          // 0 .. 65535
    const int s    = gw & (SEQ - 1);
    const int bh   = gw >> 10;                       // b*HEADS + h

    const float* Kp = g_k + (size_t)bh * SEQ * DHEAD;
    const float* Vp = g_v + (size_t)bh * SEQ * DHEAD;
    const float* Qp = g_q + (size_t)bh * SEQ * DHEAD + (size_t)s * DHEAD;

    const float scale = 0.125f;                      // 1/sqrt(64)
    float q0 = Qp[lane] * scale;
    float q1 = Qp[lane + 32] * scale;

    const float NEGINF = -CUDART_INF_F;
    float l0 = NEGINF, l1 = NEGINF;
    int   i0 = 0,      i1 = 0;
    int   count = 0;

    const int t = s >> 8;
    const int r = (s >> 4) & 15;

#define PROC_NB(JEXPR)                                                        \
    {                                                                         \
        int j = (JEXPR);                                                      \
        const float* kr = Kp + ((size_t)j << 6);                              \
        float p = q0 * kr[lane] + q1 * kr[lane + 32];                         \
        p += __shfl_xor_sync(FULLMASK, p, 16);                                \
        p += __shfl_xor_sync(FULLMASK, p, 8);                                 \
        p += __shfl_xor_sync(FULLMASK, p, 4);                                 \
        p += __shfl_xor_sync(FULLMASK, p, 2);                                 \
        p += __shfl_xor_sync(FULLMASK, p, 1);                                 \
        if (count < 32) { if (lane == count) { l0 = p; i0 = j; } }            \
        else            { if (lane == count - 32) { l1 = p; i1 = j; } }       \
        count++;                                                              \
    }

    int dmax = min(LOCALB, s);
    for (int d = 0; d <= dmax; ++d) PROC_NB(s - d);
    for (int m = 2; m <= r; ++m)    PROC_NB(s - 16 * m);
    for (int m = 1; m <= t; ++m)    PROC_NB(s - 256 * m);
#undef PROC_NB

    // softmax over lane-distributed logits
    float mx = fmaxf(l0, l1);
    mx = fmaxf(mx, __shfl_xor_sync(FULLMASK, mx, 16));
    mx = fmaxf(mx, __shfl_xor_sync(FULLMASK, mx, 8));
    mx = fmaxf(mx, __shfl_xor_sync(FULLMASK, mx, 4));
    mx = fmaxf(mx, __shfl_xor_sync(FULLMASK, mx, 2));
    mx = fmaxf(mx, __shfl_xor_sync(FULLMASK, mx, 1));

    float e0 = __expf(l0 - mx);   // -inf -> 0
    float e1 = __expf(l1 - mx);
    float ssum = e0 + e1;
    ssum += __shfl_xor_sync(FULLMASK, ssum, 16);
    ssum += __shfl_xor_sync(FULLMASK, ssum, 8);
    ssum += __shfl_xor_sync(FULLMASK, ssum, 4);
    ssum += __shfl_xor_sync(FULLMASK, ssum, 2);
    ssum += __shfl_xor_sync(FULLMASK, ssum, 1);

    float acc0 = 0.f, acc1 = 0.f;
    for (int n = 0; n < count; ++n) {
        float e = (n < 32) ? e0 : e1;
        int   jj = (n < 32) ? i0 : i1;
        float p = __shfl_sync(FULLMASK, e, n & 31);
        int   j = __shfl_sync(FULLMASK, jj, n & 31);
        const float* vr = Vp + ((size_t)j << 6);
        acc0 = fmaf(p, vr[lane], acc0);
        acc1 = fmaf(p, vr[lane + 32], acc1);
    }

    float inv = 1.0f / ssum;
    int b = bh >> 3, h = bh & 7;
    size_t o = ((size_t)(b * SEQ + s) * DIM) + h * DHEAD + lane;
    g_att[o]      = acc0 * inv;
    g_att[o + 32] = acc1 * inv;
}

// ---------------------------------------------------------------------------
extern "C" void kernel_launch(void* const* d_in, const int* in_sizes, int n_in,
                              void* d_out, int out_size)
{
    const float* query = (const float*)d_in[0];
    const float* key   = (const float*)d_in[1];
    const float* value = (const float*)d_in[2];
    const float* Wq    = (const float*)d_in[3];
    const float* bq    = (const float*)d_in[4];
    const float* Wk    = (const float*)d_in[5];
    const float* bk    = (const float*)d_in[6];
    const float* Wv    = (const float*)d_in[7];
    const float* bv    = (const float*)d_in[8];
    const float* Wo    = (const float*)d_in[9];
    const float* bo    = (const float*)d_in[10];
    float* out = (float*)d_out;

    dim3 blk(256);
    dim3 gridP(DIM / 128, MROWS / 128, 3);   // 4 x 64 x 3
    proj_qkv_kernel<<<gridP, blk>>>(query, key, value, Wq, Wk, Wv, bq, bk, bv);

    dim3 gridA(BATCH * HEADS * SEQ / 8);     // 8192 blocks, 8 warps each
    sparse_attn_kernel<<<gridA, blk>>>();

    dim3 gridO(DIM / 128, MROWS / 128);      // 4 x 64
    out_proj_kernel<<<gridO, blk>>>(Wo, bo, out);
}

// round 3
// speedup vs baseline: 2.7738x; 2.7738x over previous
#include <cuda_runtime.h>
#include <cuda_bf16.h>
#include <math_constants.h>
#include <cstdint>
#include <cstddef>

// Problem constants
#define BATCH   8
#define SEQ     1024
#define DIM     512
#define HEADS   8
#define DHEAD   64
#define MROWS   (BATCH * SEQ)        // 8192
#define LOCALB  16

// Scratch (device globals; allocation is forbidden)
__device__ float g_q[MROWS * DIM];    // head-split [b][h][s][d]
__device__ float g_k[MROWS * DIM];
__device__ float g_v[MROWS * DIM];
__device__ float g_att[MROWS * DIM];  // merged-head [b][s][h*64+d]

// ---------------------------------------------------------------------------
// tf32 tensor-core GEMM: C[M,512] = A[M,512] @ W[512,512] + bias
// 128x128 block tile, BK=16, double-buffered smem + register prefetch.
// 8 warps, each 64x32 (4x4 tiles of m16n8k8 tf32 mma).
// ---------------------------------------------------------------------------
#define BK 16
#define APITCH 20
#define BPITCH 136

__device__ __forceinline__ uint32_t f2tf32(float f) {
    uint32_t r;
    asm("cvt.rna.tf32.f32 %0, %1;" : "=r"(r) : "f"(f));
    return r;
}

__device__ __forceinline__ void mma_tf32(
    float& c0, float& c1, float& c2, float& c3,
    uint32_t a0, uint32_t a1, uint32_t a2, uint32_t a3,
    uint32_t b0, uint32_t b1)
{
    asm volatile(
        "mma.sync.aligned.m16n8k8.row.col.f32.tf32.tf32.f32 "
        "{%0,%1,%2,%3}, {%4,%5,%6,%7}, {%8,%9}, {%0,%1,%2,%3};"
        : "+f"(c0), "+f"(c1), "+f"(c2), "+f"(c3)
        : "r"(a0), "r"(a1), "r"(a2), "r"(a3), "r"(b0), "r"(b1));
}

__device__ __forceinline__ void gemm_tf32_body(
    const float* __restrict__ A, const float* __restrict__ W,
    const float* __restrict__ bias, float* __restrict__ C,
    int headsplit, int bx, int by)
{
    __shared__ float As[2][128][APITCH];
    __shared__ float Bs[2][BK][BPITCH];

    const int tid  = threadIdx.x;
    const int warp = tid >> 5;
    const int lane = tid & 31;
    const int g    = lane >> 2;      // groupID 0..7
    const int tig  = lane & 3;       // thread-in-group 0..3

    const int warp_m = warp >> 2;    // 0..1  -> rows warp_m*64
    const int warp_n = warp & 3;     // 0..3  -> cols warp_n*32

    const float* Aptr = A + (size_t)(by * 128) * DIM;
    const float* Wptr = W + bx * 128;

    // global-load thread mapping
    const int arow = tid >> 2;             // 0..63 (+64 for second)
    const int ac4  = (tid & 3) * 4;        // 0,4,8,12
    const int brow = tid >> 5;             // 0..7  (+8 for second)
    const int bc4  = (tid & 31) * 4;       // 0..124

    float c[4][4][4];
#pragma unroll
    for (int i = 0; i < 4; i++)
#pragma unroll
        for (int j = 0; j < 4; j++)
#pragma unroll
            for (int r = 0; r < 4; r++) c[i][j][r] = 0.f;

    float4 ra0, ra1, rb0, rb1;

    auto loadG = [&](int k0) {
        ra0 = *(const float4*)(Aptr + (size_t)arow * DIM + k0 + ac4);
        ra1 = *(const float4*)(Aptr + (size_t)(arow + 64) * DIM + k0 + ac4);
        rb0 = *(const float4*)(Wptr + (size_t)(k0 + brow) * DIM + bc4);
        rb1 = *(const float4*)(Wptr + (size_t)(k0 + brow + 8) * DIM + bc4);
    };
    auto storeS = [&](int buf) {
        float4 t;
        t.x = __uint_as_float(f2tf32(ra0.x)); t.y = __uint_as_float(f2tf32(ra0.y));
        t.z = __uint_as_float(f2tf32(ra0.z)); t.w = __uint_as_float(f2tf32(ra0.w));
        *(float4*)&As[buf][arow][ac4] = t;
        t.x = __uint_as_float(f2tf32(ra1.x)); t.y = __uint_as_float(f2tf32(ra1.y));
        t.z = __uint_as_float(f2tf32(ra1.z)); t.w = __uint_as_float(f2tf32(ra1.w));
        *(float4*)&As[buf][arow + 64][ac4] = t;
        t.x = __uint_as_float(f2tf32(rb0.x)); t.y = __uint_as_float(f2tf32(rb0.y));
        t.z = __uint_as_float(f2tf32(rb0.z)); t.w = __uint_as_float(f2tf32(rb0.w));
        *(float4*)&Bs[buf][brow][bc4] = t;
        t.x = __uint_as_float(f2tf32(rb1.x)); t.y = __uint_as_float(f2tf32(rb1.y));
        t.z = __uint_as_float(f2tf32(rb1.z)); t.w = __uint_as_float(f2tf32(rb1.w));
        *(float4*)&Bs[buf][brow + 8][bc4] = t;
    };

    loadG(0);
    storeS(0);
    __syncthreads();

    const int NIT = DIM / BK;   // 32
    for (int it = 0; it < NIT; ++it) {
        const int buf = it & 1;
        if (it + 1 < NIT) loadG((it + 1) * BK);

#pragma unroll
        for (int kk = 0; kk < 2; ++kk) {
            const int kb = kk * 8;
            uint32_t af[4][4];
#pragma unroll
            for (int mi = 0; mi < 4; mi++) {
                const int rb = warp_m * 64 + mi * 16;
                af[mi][0] = __float_as_uint(As[buf][rb + g][kb + tig]);
                af[mi][1] = __float_as_uint(As[buf][rb + g + 8][kb + tig]);
                af[mi][2] = __float_as_uint(As[buf][rb + g][kb + tig + 4]);
                af[mi][3] = __float_as_uint(As[buf][rb + g + 8][kb + tig + 4]);
            }
            uint32_t bf[4][2];
#pragma unroll
            for (int nj = 0; nj < 4; nj++) {
                const int cb = warp_n * 32 + nj * 8;
                bf[nj][0] = __float_as_uint(Bs[buf][kb + tig][cb + g]);
                bf[nj][1] = __float_as_uint(Bs[buf][kb + tig + 4][cb + g]);
            }
#pragma unroll
            for (int mi = 0; mi < 4; mi++)
#pragma unroll
                for (int nj = 0; nj < 4; nj++)
                    mma_tf32(c[mi][nj][0], c[mi][nj][1], c[mi][nj][2], c[mi][nj][3],
                             af[mi][0], af[mi][1], af[mi][2], af[mi][3],
                             bf[nj][0], bf[nj][1]);
        }

        if (it + 1 < NIT) storeS((it + 1) & 1);
        __syncthreads();
    }

    // Epilogue
#pragma unroll
    for (int mi = 0; mi < 4; mi++) {
#pragma unroll
        for (int nj = 0; nj < 4; nj++) {
            const int cb = bx * 128 + warp_n * 32 + nj * 8 + tig * 2;
#pragma unroll
            for (int half = 0; half < 2; half++) {
                const int row = by * 128 + warp_m * 64 + mi * 16 + g + half * 8;
                float v0 = c[mi][nj][half * 2 + 0] + bias[cb];
                float v1 = c[mi][nj][half * 2 + 1] + bias[cb + 1];
                if (headsplit) {
                    int b = row >> 10, s = row & 1023;
                    int h = cb >> 6,  d = cb & 63;
                    size_t o = ((size_t)((b * HEADS + h) * SEQ + s) << 6) + d;
                    C[o]     = v0;
                    C[o + 1] = v1;
                } else {
                    C[(size_t)row * DIM + cb]     = v0;
                    C[(size_t)row * DIM + cb + 1] = v1;
                }
            }
        }
    }
}

__global__ __launch_bounds__(256, 2) void proj_qkv_kernel(
    const float* __restrict__ q,  const float* __restrict__ k,  const float* __restrict__ v,
    const float* __restrict__ Wq, const float* __restrict__ Wk, const float* __restrict__ Wv,
    const float* __restrict__ bq, const float* __restrict__ bk, const float* __restrict__ bv)
{
    const float* A; const float* W; const float* bias; float* C;
    if (blockIdx.z == 0)      { A = q; W = Wq; bias = bq; C = g_q; }
    else if (blockIdx.z == 1) { A = k; W = Wk; bias = bk; C = g_k; }
    else                      { A = v; W = Wv; bias = bv; C = g_v; }
    gemm_tf32_body(A, W, bias, C, 1, blockIdx.x, blockIdx.y);
}

__global__ __launch_bounds__(256, 2) void out_proj_kernel(
    const float* __restrict__ Wo, const float* __restrict__ bo, float* __restrict__ out)
{
    gemm_tf32_body(g_att, Wo, bo, out, 0, blockIdx.x, blockIdx.y);
}

// ---------------------------------------------------------------------------
// Sparse attention: one warp per (b, h, s) query.
// ---------------------------------------------------------------------------
#define FULLMASK 0xffffffffu

__global__ __launch_bounds__(256) void sparse_attn_kernel()
{
    const int warp = threadIdx.x >> 5;
    const int lane = threadIdx.x & 31;
    const int gw   = blockIdx.x * 8 + warp;          // 0 .. 65535
    const int s    = gw & (SEQ - 1);
    const int bh   = gw >> 10;                       // b*HEADS + h

    const float* Kp = g_k + (size_t)bh * SEQ * DHEAD;
    const float* Vp = g_v + (size_t)bh * SEQ * DHEAD;
    const float* Qp = g_q + (size_t)bh * SEQ * DHEAD + (size_t)s * DHEAD;

    const float scale = 0.125f;                      // 1/sqrt(64)
    float q0 = Qp[lane] * scale;
    float q1 = Qp[lane + 32] * scale;

    const float NEGINF = -CUDART_INF_F;
    float l0 = NEGINF, l1 = NEGINF;
    int   i0 = 0,      i1 = 0;
    int   count = 0;

    const int t = s >> 8;
    const int r = (s >> 4) & 15;

#define PROC_NB(JEXPR)                                                        \
    {                                                                         \
        int j = (JEXPR);                                                      \
        const float* kr = Kp + ((size_t)j << 6);                              \
        float p = q0 * kr[lane] + q1 * kr[lane + 32];                         \
        p += __shfl_xor_sync(FULLMASK, p, 16);                                \
        p += __shfl_xor_sync(FULLMASK, p, 8);                                 \
        p += __shfl_xor_sync(FULLMASK, p, 4);                                 \
        p += __shfl_xor_sync(FULLMASK, p, 2);                                 \
        p += __shfl_xor_sync(FULLMASK, p, 1);                                 \
        if (count < 32) { if (lane == count) { l0 = p; i0 = j; } }            \
        else            { if (lane == count - 32) { l1 = p; i1 = j; } }       \
        count++;                                                              \
    }

    int dmax = min(LOCALB, s);
    for (int d = 0; d <= dmax; ++d) PROC_NB(s - d);
    for (int m = 2; m <= r; ++m)    PROC_NB(s - 16 * m);
    for (int m = 1; m <= t; ++m)    PROC_NB(s - 256 * m);
#undef PROC_NB

    float mx = fmaxf(l0, l1);
    mx = fmaxf(mx, __shfl_xor_sync(FULLMASK, mx, 16));
    mx = fmaxf(mx, __shfl_xor_sync(FULLMASK, mx, 8));
    mx = fmaxf(mx, __shfl_xor_sync(FULLMASK, mx, 4));
    mx = fmaxf(mx, __shfl_xor_sync(FULLMASK, mx, 2));
    mx = fmaxf(mx, __shfl_xor_sync(FULLMASK, mx, 1));

    float e0 = __expf(l0 - mx);
    float e1 = __expf(l1 - mx);
    float ssum = e0 + e1;
    ssum += __shfl_xor_sync(FULLMASK, ssum, 16);
    ssum += __shfl_xor_sync(FULLMASK, ssum, 8);
    ssum += __shfl_xor_sync(FULLMASK, ssum, 4);
    ssum += __shfl_xor_sync(FULLMASK, ssum, 2);
    ssum += __shfl_xor_sync(FULLMASK, ssum, 1);

    float acc0 = 0.f, acc1 = 0.f;
    for (int n = 0; n < count; ++n) {
        float e = (n < 32) ? e0 : e1;
        int   jj = (n < 32) ? i0 : i1;
        float p = __shfl_sync(FULLMASK, e, n & 31);
        int   j = __shfl_sync(FULLMASK, jj, n & 31);
        const float* vr = Vp + ((size_t)j << 6);
        acc0 = fmaf(p, vr[lane], acc0);
        acc1 = fmaf(p, vr[lane + 32], acc1);
    }

    float inv = 1.0f / ssum;
    int b = bh >> 3, h = bh & 7;
    size_t o = ((size_t)(b * SEQ + s) * DIM) + h * DHEAD + lane;
    g_att[o]      = acc0 * inv;
    g_att[o + 32] = acc1 * inv;
}

// ---------------------------------------------------------------------------
extern "C" void kernel_launch(void* const* d_in, const int* in_sizes, int n_in,
                              void* d_out, int out_size)
{
    const float* query = (const float*)d_in[0];
    const float* key   = (const float*)d_in[1];
    const float* value = (const float*)d_in[2];
    const float* Wq    = (const float*)d_in[3];
    const float* bq    = (const float*)d_in[4];
    const float* Wk    = (const float*)d_in[5];
    const float* bk    = (const float*)d_in[6];
    const float* Wv    = (const float*)d_in[7];
    const float* bv    = (const float*)d_in[8];
    const float* Wo    = (const float*)d_in[9];
    const float* bo    = (const float*)d_in[10];
    float* out = (float*)d_out;

    dim3 blk(256);
    dim3 gridP(DIM / 128, MROWS / 128, 3);   // 4 x 64 x 3
    proj_qkv_kernel<<<gridP, blk>>>(query, key, value, Wq, Wk, Wv, bq, bk, bv);

    dim3 gridA(BATCH * HEADS * SEQ / 8);     // 8192 blocks, 8 warps each
    sparse_attn_kernel<<<gridA, blk>>>();

    dim3 gridO(DIM / 128, MROWS / 128);      // 4 x 64
    out_proj_kernel<<<gridO, blk>>>(Wo, bo, out);
}

// round 5
// speedup vs baseline: 2.9055x; 1.0475x over previous
#include <cuda_runtime.h>
#include <cuda_bf16.h>
#include <math_constants.h>
#include <cstdint>
#include <cstddef>

// Problem constants
#define BATCH   8
#define SEQ     1024
#define DIM     512
#define HEADS   8
#define DHEAD   64
#define MROWS   (BATCH * SEQ)        // 8192
#define LOCALB  16

// Scratch (device globals; allocation is forbidden)
__device__ float g_q[MROWS * DIM];    // head-split [b][h][s][d]
__device__ float g_k[MROWS * DIM];
__device__ float g_v[MROWS * DIM];
__device__ float g_att[MROWS * DIM];  // merged-head [b][s][h*64+d]

// ---------------------------------------------------------------------------
// tf32 tensor-core GEMM: C[M,512] = A[M,512] @ W[512,512] + bias
// 128x128 block tile, BK=16, double-buffered smem + register prefetch.
// 8 warps, each 64x32 (4x4 tiles of m16n8k8 tf32 mma).   (R3 proven-good)
// ---------------------------------------------------------------------------
#define BK 16
#define APITCH 20
#define BPITCH 136

__device__ __forceinline__ uint32_t f2tf32(float f) {
    uint32_t r;
    asm("cvt.rna.tf32.f32 %0, %1;" : "=r"(r) : "f"(f));
    return r;
}

__device__ __forceinline__ void mma_tf32(
    float& c0, float& c1, float& c2, float& c3,
    uint32_t a0, uint32_t a1, uint32_t a2, uint32_t a3,
    uint32_t b0, uint32_t b1)
{
    asm volatile(
        "mma.sync.aligned.m16n8k8.row.col.f32.tf32.tf32.f32 "
        "{%0,%1,%2,%3}, {%4,%5,%6,%7}, {%8,%9}, {%0,%1,%2,%3};"
        : "+f"(c0), "+f"(c1), "+f"(c2), "+f"(c3)
        : "r"(a0), "r"(a1), "r"(a2), "r"(a3), "r"(b0), "r"(b1));
}

__device__ __forceinline__ void gemm_tf32_body(
    const float* __restrict__ A, const float* __restrict__ W,
    const float* __restrict__ bias, float* __restrict__ C,
    int headsplit, int bx, int by)
{
    __shared__ float As[2][128][APITCH];
    __shared__ float Bs[2][BK][BPITCH];

    const int tid  = threadIdx.x;
    const int warp = tid >> 5;
    const int lane = tid & 31;
    const int g    = lane >> 2;      // groupID 0..7
    const int tig  = lane & 3;       // thread-in-group 0..3

    const int warp_m = warp >> 2;    // 0..1  -> rows warp_m*64
    const int warp_n = warp & 3;     // 0..3  -> cols warp_n*32

    const float* Aptr = A + (size_t)(by * 128) * DIM;
    const float* Wptr = W + bx * 128;

    const int arow = tid >> 2;             // 0..63 (+64 for second)
    const int ac4  = (tid & 3) * 4;        // 0,4,8,12
    const int brow = tid >> 5;             // 0..7  (+8 for second)
    const int bc4  = (tid & 31) * 4;       // 0..124

    float c[4][4][4];
#pragma unroll
    for (int i = 0; i < 4; i++)
#pragma unroll
        for (int j = 0; j < 4; j++)
#pragma unroll
            for (int r = 0; r < 4; r++) c[i][j][r] = 0.f;

    float4 ra0, ra1, rb0, rb1;

    auto loadG = [&](int k0) {
        ra0 = *(const float4*)(Aptr + (size_t)arow * DIM + k0 + ac4);
        ra1 = *(const float4*)(Aptr + (size_t)(arow + 64) * DIM + k0 + ac4);
        rb0 = *(const float4*)(Wptr + (size_t)(k0 + brow) * DIM + bc4);
        rb1 = *(const float4*)(Wptr + (size_t)(k0 + brow + 8) * DIM + bc4);
    };
    auto storeS = [&](int buf) {
        float4 t;
        t.x = __uint_as_float(f2tf32(ra0.x)); t.y = __uint_as_float(f2tf32(ra0.y));
        t.z = __uint_as_float(f2tf32(ra0.z)); t.w = __uint_as_float(f2tf32(ra0.w));
        *(float4*)&As[buf][arow][ac4] = t;
        t.x = __uint_as_float(f2tf32(ra1.x)); t.y = __uint_as_float(f2tf32(ra1.y));
        t.z = __uint_as_float(f2tf32(ra1.z)); t.w = __uint_as_float(f2tf32(ra1.w));
        *(float4*)&As[buf][arow + 64][ac4] = t;
        t.x = __uint_as_float(f2tf32(rb0.x)); t.y = __uint_as_float(f2tf32(rb0.y));
        t.z = __uint_as_float(f2tf32(rb0.z)); t.w = __uint_as_float(f2tf32(rb0.w));
        *(float4*)&Bs[buf][brow][bc4] = t;
        t.x = __uint_as_float(f2tf32(rb1.x)); t.y = __uint_as_float(f2tf32(rb1.y));
        t.z = __uint_as_float(f2tf32(rb1.z)); t.w = __uint_as_float(f2tf32(rb1.w));
        *(float4*)&Bs[buf][brow + 8][bc4] = t;
    };

    loadG(0);
    storeS(0);
    __syncthreads();

    const int NIT = DIM / BK;   // 32
    for (int it = 0; it < NIT; ++it) {
        const int buf = it & 1;
        if (it + 1 < NIT) loadG((it + 1) * BK);

#pragma unroll
        for (int kk = 0; kk < 2; ++kk) {
            const int kb = kk * 8;
            uint32_t af[4][4];
#pragma unroll
            for (int mi = 0; mi < 4; mi++) {
                const int rb = warp_m * 64 + mi * 16;
                af[mi][0] = __float_as_uint(As[buf][rb + g][kb + tig]);
                af[mi][1] = __float_as_uint(As[buf][rb + g + 8][kb + tig]);
                af[mi][2] = __float_as_uint(As[buf][rb + g][kb + tig + 4]);
                af[mi][3] = __float_as_uint(As[buf][rb + g + 8][kb + tig + 4]);
            }
            uint32_t bf[4][2];
#pragma unroll
            for (int nj = 0; nj < 4; nj++) {
                const int cb = warp_n * 32 + nj * 8;
                bf[nj][0] = __float_as_uint(Bs[buf][kb + tig][cb + g]);
                bf[nj][1] = __float_as_uint(Bs[buf][kb + tig + 4][cb + g]);
            }
#pragma unroll
            for (int mi = 0; mi < 4; mi++)
#pragma unroll
                for (int nj = 0; nj < 4; nj++)
                    mma_tf32(c[mi][nj][0], c[mi][nj][1], c[mi][nj][2], c[mi][nj][3],
                             af[mi][0], af[mi][1], af[mi][2], af[mi][3],
                             bf[nj][0], bf[nj][1]);
        }

        if (it + 1 < NIT) storeS((it + 1) & 1);
        __syncthreads();
    }

    // Epilogue
#pragma unroll
    for (int mi = 0; mi < 4; mi++) {
#pragma unroll
        for (int nj = 0; nj < 4; nj++) {
            const int cb = bx * 128 + warp_n * 32 + nj * 8 + tig * 2;
#pragma unroll
            for (int half = 0; half < 2; half++) {
                const int row = by * 128 + warp_m * 64 + mi * 16 + g + half * 8;
                float v0 = c[mi][nj][half * 2 + 0] + bias[cb];
                float v1 = c[mi][nj][half * 2 + 1] + bias[cb + 1];
                if (headsplit) {
                    int b = row >> 10, s = row & 1023;
                    int h = cb >> 6,  d = cb & 63;
                    size_t o = ((size_t)((b * HEADS + h) * SEQ + s) << 6) + d;
                    C[o]     = v0;
                    C[o + 1] = v1;
                } else {
                    C[(size_t)row * DIM + cb]     = v0;
                    C[(size_t)row * DIM + cb + 1] = v1;
                }
            }
        }
    }
}

__global__ __launch_bounds__(256, 2) void proj_qkv_kernel(
    const float* __restrict__ q,  const float* __restrict__ k,  const float* __restrict__ v,
    const float* __restrict__ Wq, const float* __restrict__ Wk, const float* __restrict__ Wv,
    const float* __restrict__ bq, const float* __restrict__ bk, const float* __restrict__ bv)
{
    const float* A; const float* W; const float* bias; float* C;
    if (blockIdx.z == 0)      { A = q; W = Wq; bias = bq; C = g_q; }
    else if (blockIdx.z == 1) { A = k; W = Wk; bias = bk; C = g_k; }
    else                      { A = v; W = Wv; bias = bv; C = g_v; }
    gemm_tf32_body(A, W, bias, C, 1, blockIdx.x, blockIdx.y);
}

__global__ __launch_bounds__(256, 2) void out_proj_kernel(
    const float* __restrict__ Wo, const float* __restrict__ bo, float* __restrict__ out)
{
    gemm_tf32_body(g_att, Wo, bo, out, 0, blockIdx.x, blockIdx.y);
}

// ---------------------------------------------------------------------------
// Sparse attention, band-tiled:
// Block = 1024 threads = 32 warps = 32 consecutive queries of one (b,h).
// K/V band rows [s0-16, s0+31] (48 rows) staged in smem; band neighbors
// (17/query) served from smem, row/frame-strided neighbors from global.
// ---------------------------------------------------------------------------
#define FULLMASK 0xffffffffu
#define AQ 32                         // queries per block
#define BANDROWS (AQ + LOCALB)        // 48

__global__ __launch_bounds__(1024) void sparse_attn_kernel()
{
    __shared__ float Kb[BANDROWS][DHEAD];
    __shared__ float Vb[BANDROWS][DHEAD];

    const int warp = threadIdx.x >> 5;
    const int lane = threadIdx.x & 31;
    const int s0   = (blockIdx.x & (SEQ / AQ - 1)) * AQ;   // 0..992
    const int bh   = blockIdx.x / (SEQ / AQ);              // b*HEADS + h
    const int base = s0 - LOCALB;                          // may be negative

    const float* Kp = g_k + (size_t)bh * SEQ * DHEAD;
    const float* Vp = g_v + (size_t)bh * SEQ * DHEAD;

    // stage band rows (float4): 48 rows x 16 float4 x {K,V} = 1536 tasks
    for (int task = threadIdx.x; task < BANDROWS * 16 * 2; task += 1024) {
        int which = task >= BANDROWS * 16;           // 0=K, 1=V
        int t     = which ? task - BANDROWS * 16 : task;
        int row   = t >> 4;
        int c4    = (t & 15) * 4;
        int j     = base + row;
        if (j >= 0) {
            const float* src = (which ? Vp : Kp) + ((size_t)j << 6) + c4;
            float4 val = *(const float4*)src;
            float* dst = which ? &Vb[row][c4] : &Kb[row][c4];
            *(float4*)dst = val;
        }
    }
    __syncthreads();

    const int s  = s0 + warp;
    const float* Qp = g_q + (size_t)bh * SEQ * DHEAD + ((size_t)s << 6);

    const float scale = 0.125f;                      // 1/sqrt(64)
    float q0 = Qp[lane] * scale;
    float q1 = Qp[lane + 32] * scale;

    const float NEGINF = -CUDART_INF_F;
    float l0 = NEGINF, l1 = NEGINF;
    int   i0 = 0,      i1 = 0;
    int   count = 0;

    const int t = s >> 8;
    const int r = (s >> 4) & 15;

#define PROC_ROW(KRPTR, JIDX)                                                 \
    {                                                                         \
        const float* kr = (KRPTR);                                            \
        float p = q0 * kr[lane] + q1 * kr[lane + 32];                         \
        p += __shfl_xor_sync(FULLMASK, p, 16);                                \
        p += __shfl_xor_sync(FULLMASK, p, 8);                                 \
        p += __shfl_xor_sync(FULLMASK, p, 4);                                 \
        p += __shfl_xor_sync(FULLMASK, p, 2);                                 \
        p += __shfl_xor_sync(FULLMASK, p, 1);                                 \
        if (count < 32) { if (lane == count) { l0 = p; i0 = (JIDX); } }       \
        else            { if (lane == count - 32) { l1 = p; i1 = (JIDX); } }  \
        count++;                                                              \
    }

    const int dmax  = min(LOCALB, s);
    const int nBand = dmax + 1;
    // band neighbors from smem: j = s - d  -> smem row = warp + 16 - d
    for (int d = 0; d <= dmax; ++d) PROC_ROW(&Kb[warp + LOCALB - d][0], s - d);
    // row-strided + frame-strided from global
    for (int m = 2; m <= r; ++m)    PROC_ROW(Kp + ((size_t)(s - 16 * m) << 6), s - 16 * m);
    for (int m = 1; m <= t; ++m)    PROC_ROW(Kp + ((size_t)(s - 256 * m) << 6), s - 256 * m);
#undef PROC_ROW

    // softmax over lane-distributed logits
    float mx = fmaxf(l0, l1);
    mx = fmaxf(mx, __shfl_xor_sync(FULLMASK, mx, 16));
    mx = fmaxf(mx, __shfl_xor_sync(FULLMASK, mx, 8));
    mx = fmaxf(mx, __shfl_xor_sync(FULLMASK, mx, 4));
    mx = fmaxf(mx, __shfl_xor_sync(FULLMASK, mx, 2));
    mx = fmaxf(mx, __shfl_xor_sync(FULLMASK, mx, 1));

    float e0 = __expf(l0 - mx);
    float e1 = __expf(l1 - mx);
    float ssum = e0 + e1;
    ssum += __shfl_xor_sync(FULLMASK, ssum, 16);
    ssum += __shfl_xor_sync(FULLMASK, ssum, 8);
    ssum += __shfl_xor_sync(FULLMASK, ssum, 4);
    ssum += __shfl_xor_sync(FULLMASK, ssum, 2);
    ssum += __shfl_xor_sync(FULLMASK, ssum, 1);

    float acc0 = 0.f, acc1 = 0.f;
    // band entries: n in [0, nBand) -> V from smem row warp+16-n
    for (int n = 0; n < nBand; ++n) {
        float p = __shfl_sync(FULLMASK, e0, n);
        const float* vr = &Vb[warp + LOCALB - n][0];
        acc0 = fmaf(p, vr[lane], acc0);
        acc1 = fmaf(p, vr[lane + 32], acc1);
    }
    // remaining entries from global
    for (int n = nBand; n < count; ++n) {
        float e = (n < 32) ? e0 : e1;
        int   jj = (n < 32) ? i0 : i1;
        float p = __shfl_sync(FULLMASK, e, n & 31);
        int   j = __shfl_sync(FULLMASK, jj, n & 31);
        const float* vr = Vp + ((size_t)j << 6);
        acc0 = fmaf(p, vr[lane], acc0);
        acc1 = fmaf(p, vr[lane + 32], acc1);
    }

    float inv = 1.0f / ssum;
    int b = bh >> 3, h = bh & 7;
    size_t o = ((size_t)(b * SEQ + s) * DIM) + h * DHEAD + lane;
    g_att[o]      = acc0 * inv;
    g_att[o + 32] = acc1 * inv;
}

// ---------------------------------------------------------------------------
extern "C" void kernel_launch(void* const* d_in, const int* in_sizes, int n_in,
                              void* d_out, int out_size)
{
    const float* query = (const float*)d_in[0];
    const float* key   = (const float*)d_in[1];
    const float* value = (const float*)d_in[2];
    const float* Wq    = (const float*)d_in[3];
    const float* bq    = (const float*)d_in[4];
    const float* Wk    = (const float*)d_in[5];
    const float* bk    = (const float*)d_in[6];
    const float* Wv    = (const float*)d_in[7];
    const float* bv    = (const float*)d_in[8];
    const float* Wo    = (const float*)d_in[9];
    const float* bo    = (const float*)d_in[10];
    float* out = (float*)d_out;

    dim3 blk(256);
    dim3 gridP(DIM / 128, MROWS / 128, 3);   // 4 x 64 x 3
    proj_qkv_kernel<<<gridP, blk>>>(query, key, value, Wq, Wk, Wv, bq, bk, bv);

    dim3 gridA(BATCH * HEADS * (SEQ / AQ));  // 2048 blocks, 1024 threads
    sparse_attn_kernel<<<gridA, dim3(1024)>>>();

    dim3 gridO(DIM / 128, MROWS / 128);      // 4 x 64
    out_proj_kernel<<<gridO, blk>>>(Wo, bo, out);
}